// round 2
// baseline (speedup 1.0000x reference)
#include <cuda_runtime.h>

// Problem constants (fixed shapes for this problem instance)
#define NN 100000   // nodes
#define NE 800000   // edges
#define VC 256      // vocab
#define DM 256      // node dim == hidden == vocab
#define NM 10000    // masked outputs

// ---------------- scratch (device globals; no allocation allowed) ----------
__device__ int   g_deg[NN];
__device__ float g_dinv[NN];
__device__ int   g_masked[NN];
__device__ float g_EW[VC * DM];            // emb @ W1  (256 KB)
__device__ float g_out1[NN * DM];          // layer-1 pre-activation (102 MB)
__device__ float g_agg1[NN * DM];          // layer-2 aggregate, masked rows only

__device__ __forceinline__ void red_add_v4(float* addr, float4 v) {
    asm volatile("red.global.add.v4.f32 [%0], {%1, %2, %3, %4};"
                 :: "l"(addr), "f"(v.x), "f"(v.y), "f"(v.z), "f"(v.w)
                 : "memory");
}

// ---------------- kernels ---------------------------------------------------

// deg = 1 (self loop), masked = 0
__global__ void k_init(void) {
    int i = blockIdx.x * blockDim.x + threadIdx.x;
    if (i < NN) { g_deg[i] = 1; g_masked[i] = 0; }
}

// deg[dst] += 1 per edge
__global__ void k_deg(const int* __restrict__ ei) {
    int e = blockIdx.x * blockDim.x + threadIdx.x;
    if (e < NE) atomicAdd(&g_deg[ei[NE + e]], 1);
}

// mark masked nodes (idempotent stores; duplicates benign)
__global__ void k_mark(const int* __restrict__ mask) {
    int j = blockIdx.x * blockDim.x + threadIdx.x;
    if (j < NM) g_masked[mask[j]] = 1;
}

// dinv = rsqrt(deg)  (deg >= 1 always due to self loop)
__global__ void k_dinv(void) {
    int i = blockIdx.x * blockDim.x + threadIdx.x;
    if (i < NN) g_dinv[i] = rsqrtf((float)g_deg[i]);
}

// EW = emb @ W1 : one block per emb row, emb row staged in smem
__global__ void k_ew(const float* __restrict__ emb, const float* __restrict__ W1) {
    __shared__ float row[DM];
    int r = blockIdx.x, c = threadIdx.x;
    row[c] = emb[r * DM + c];
    __syncthreads();
    float acc = 0.f;
#pragma unroll 8
    for (int k = 0; k < DM; k++) acc += row[k] * W1[k * DM + c];
    g_EW[r * DM + c] = acc;
}

// out1[i] = b1 + dinv[i]^2 * EW[x[i]]   (bias + layer-1 self-loop message)
__global__ void k_init_out1(const int* __restrict__ x, const float* __restrict__ b1) {
    int i = blockIdx.x, c = threadIdx.x;
    int   xi = x[i];
    float d  = g_dinv[i];
    g_out1[i * DM + c] = b1[c] + d * d * g_EW[xi * DM + c];
}

// layer-1 edge scatter: out1[dst] += dinv[src]*dinv[dst] * EW[x[src]]
// 64 threads per edge, float4 per thread, vectorized reduction atomics
__global__ void k_scatter1(const int* __restrict__ ei, const int* __restrict__ x) {
    int tid = blockIdx.x * blockDim.x + threadIdx.x;
    int e = tid >> 6;
    if (e >= NE) return;
    int q = tid & 63;
    int s = ei[e];
    int d = ei[NE + e];
    float coef = g_dinv[s] * g_dinv[d];
    int   xs   = x[s];
    float4 w = reinterpret_cast<const float4*>(g_EW)[xs * (DM / 4) + q];
    float4 m = make_float4(w.x * coef, w.y * coef, w.z * coef, w.w * coef);
    red_add_v4(&g_out1[d * DM + q * 4], m);
}

// layer-2 self loop into masked rows: agg1[node] = dinv^2 * relu(out1[node])
// (duplicate mask entries write identical values before any adds -> benign)
__global__ void k_self2(const int* __restrict__ mask) {
    int j = blockIdx.x, c = threadIdx.x;
    int node = mask[j];
    float dd = g_dinv[node]; dd *= dd;
    g_agg1[node * DM + c] = dd * fmaxf(g_out1[node * DM + c], 0.f);
}

// layer-2 edge scatter, masked destinations only:
//   agg1[dst] += dinv[src]*dinv[dst] * relu(out1[src])
__global__ void k_scatter2(const int* __restrict__ ei) {
    int tid = blockIdx.x * blockDim.x + threadIdx.x;
    int e = tid >> 6;
    if (e >= NE) return;
    int d = ei[NE + e];
    if (!g_masked[d]) return;          // uniform per 64-thread group (warp-uniform)
    int q = tid & 63;
    int s = ei[e];
    float coef = g_dinv[s] * g_dinv[d];
    float4 h = reinterpret_cast<const float4*>(g_out1)[s * (DM / 4) + q];
    float4 m = make_float4(fmaxf(h.x, 0.f) * coef, fmaxf(h.y, 0.f) * coef,
                           fmaxf(h.z, 0.f) * coef, fmaxf(h.w, 0.f) * coef);
    red_add_v4(&g_agg1[d * DM + q * 4], m);
}

// final: out[j] = log_softmax(agg1[mask[j]] @ W2 + b2)
// 16 output rows per block; A tile in smem (broadcast reads), W2 streamed from L2
#define FROWS 16
__global__ void k_final(const int* __restrict__ mask,
                        const float* __restrict__ W2,
                        const float* __restrict__ b2,
                        float* __restrict__ out) {
    __shared__ float A[FROWS * DM];
    __shared__ float red[8];
    int c  = threadIdx.x;
    int j0 = blockIdx.x * FROWS;

#pragma unroll
    for (int r = 0; r < FROWS; r++) {
        int node = mask[j0 + r];
        A[r * DM + c] = g_agg1[node * DM + c];
    }
    __syncthreads();

    float bc = b2[c];
    float acc[FROWS];
#pragma unroll
    for (int r = 0; r < FROWS; r++) acc[r] = bc;

    const float4* A4 = reinterpret_cast<const float4*>(A);
#pragma unroll 4
    for (int kk = 0; kk < DM / 4; kk++) {
        float w0 = W2[(4 * kk + 0) * DM + c];
        float w1 = W2[(4 * kk + 1) * DM + c];
        float w2 = W2[(4 * kk + 2) * DM + c];
        float w3 = W2[(4 * kk + 3) * DM + c];
#pragma unroll
        for (int r = 0; r < FROWS; r++) {
            float4 a = A4[r * (DM / 4) + kk];
            acc[r] += a.x * w0 + a.y * w1 + a.z * w2 + a.w * w3;
        }
    }

    int lane = c & 31, wid = c >> 5;
#pragma unroll 1
    for (int r = 0; r < FROWS; r++) {
        // block max
        float v = acc[r];
#pragma unroll
        for (int o = 16; o; o >>= 1) v = fmaxf(v, __shfl_xor_sync(0xffffffffu, v, o));
        if (lane == 0) red[wid] = v;
        __syncthreads();
        float m = red[0];
#pragma unroll
        for (int w = 1; w < 8; w++) m = fmaxf(m, red[w]);
        __syncthreads();
        // block sum of exp
        float s = __expf(acc[r] - m);
#pragma unroll
        for (int o = 16; o; o >>= 1) s += __shfl_xor_sync(0xffffffffu, s, o);
        if (lane == 0) red[wid] = s;
        __syncthreads();
        float tot = red[0];
#pragma unroll
        for (int w = 1; w < 8; w++) tot += red[w];
        __syncthreads();
        out[(j0 + r) * DM + c] = acc[r] - m - logf(tot);
    }
}

// ---------------- launch -----------------------------------------------------
extern "C" void kernel_launch(void* const* d_in, const int* in_sizes, int n_in,
                              void* d_out, int out_size) {
    const int*   x    = (const int*)d_in[0];   // (100000,1) int32
    const int*   ei   = (const int*)d_in[1];   // (2,800000) int32: [src | dst]
    const int*   mask = (const int*)d_in[2];   // (10000,)   int32
    const float* emb  = (const float*)d_in[3]; // (256,256)
    const float* W1   = (const float*)d_in[4]; // (256,256)
    const float* b1   = (const float*)d_in[5]; // (256,)
    const float* W2   = (const float*)d_in[6]; // (256,256)
    const float* b2   = (const float*)d_in[7]; // (256,)
    float* out = (float*)d_out;                // (10000,256)

    (void)in_sizes; (void)n_in; (void)out_size;

    k_init<<<(NN + 255) / 256, 256>>>();
    k_deg <<<(NE + 255) / 256, 256>>>(ei);
    k_mark<<<(NM + 255) / 256, 256>>>(mask);
    k_dinv<<<(NN + 255) / 256, 256>>>();
    k_ew  <<<VC, DM>>>(emb, W1);
    k_init_out1<<<NN, DM>>>(x, b1);
    k_scatter1<<<(NE * 64 + 255) / 256, 256>>>(ei, x);
    k_self2   <<<NM, DM>>>(mask);
    k_scatter2<<<(NE * 64 + 255) / 256, 256>>>(ei);
    k_final   <<<NM / FROWS, DM>>>(mask, W2, b2, out);
}

// round 3
// speedup vs baseline: 2.7123x; 2.7123x over previous
#include <cuda_runtime.h>

// Problem constants (fixed shapes for this problem instance)
#define NN 100000   // nodes
#define NE 800000   // edges
#define VC 256      // vocab
#define DM 256      // node dim == hidden == vocab
#define NM 10000    // masked outputs

#define SB 512
#define NSB ((NN + SB - 1) / SB)   // 196 scan blocks

// ---------------- scratch (device globals; no allocation allowed) ----------
__device__ int   g_deg[NN];
__device__ int   g_cur[NN];
__device__ int   g_off[NN];
__device__ int   g_bsum[NSB];
__device__ float g_dinv[NN];
__device__ int   g_masked[NN];
__device__ int   g_needed[NN];
__device__ __align__(16) float g_EW[VC * DM];      // emb @ W1 (256 KB)
__device__ __align__(16) float g_out1[NN * DM];    // layer-1 pre-activation (102 MB)
__device__ __align__(16) float g_aggc[NM * DM];    // layer-2 aggregate, compact (10 MB)
// CSR payload (incoming edges grouped by dst)
__device__ int   g_ex[NE];      // x[src]
__device__ int   g_esrc[NE];    // src node
__device__ float g_ecoef[NE];   // dinv[src]*dinv[dst]

// ---------------- kernels ---------------------------------------------------

__global__ void k_init(void) {
    int i = blockIdx.x * blockDim.x + threadIdx.x;
    if (i < NN) { g_deg[i] = 1; g_cur[i] = 0; g_masked[i] = 0; g_needed[i] = 0; }
}

__global__ void k_deg(const int* __restrict__ ei) {
    int e = blockIdx.x * blockDim.x + threadIdx.x;
    if (e < NE) atomicAdd(&g_deg[ei[NE + e]], 1);
}

// masked nodes are also "needed" (self term of layer-2 reads out1[node])
__global__ void k_mark(const int* __restrict__ mask) {
    int j = blockIdx.x * blockDim.x + threadIdx.x;
    if (j < NM) { int n = mask[j]; g_masked[n] = 1; g_needed[n] = 1; }
}

__global__ void k_dinv(void) {
    int i = blockIdx.x * blockDim.x + threadIdx.x;
    if (i < NN) g_dinv[i] = rsqrtf((float)g_deg[i]);
}

// ---- exclusive prefix scan of (deg-1) -> CSR row offsets -------------------
__global__ void k_scanA(void) {
    __shared__ int s[SB];
    int i = blockIdx.x * SB + threadIdx.x;
    int v = (i < NN) ? (g_deg[i] - 1) : 0;
    s[threadIdx.x] = v;
    __syncthreads();
    for (int o = 1; o < SB; o <<= 1) {
        int t = (threadIdx.x >= o) ? s[threadIdx.x - o] : 0;
        __syncthreads();
        s[threadIdx.x] += t;
        __syncthreads();
    }
    int inc = s[threadIdx.x];
    if (i < NN) g_off[i] = inc - v;                 // exclusive
    if (threadIdx.x == SB - 1) g_bsum[blockIdx.x] = inc;
}

__global__ void k_scanB(void) {   // one block of 256 >= NSB
    __shared__ int s[256];
    int t = threadIdx.x;
    int v = (t < NSB) ? g_bsum[t] : 0;
    s[t] = v;
    __syncthreads();
    for (int o = 1; o < 256; o <<= 1) {
        int u = (t >= o) ? s[t - o] : 0;
        __syncthreads();
        s[t] += u;
        __syncthreads();
    }
    if (t < NSB) g_bsum[t] = s[t] - v;              // exclusive
}

__global__ void k_scanC(void) {
    int i = blockIdx.x * SB + threadIdx.x;
    if (i < NN) g_off[i] += g_bsum[blockIdx.x];
}

// EW = emb @ W1 : one block per emb row, emb row staged in smem
__global__ void k_ew(const float* __restrict__ emb, const float* __restrict__ W1) {
    __shared__ float row[DM];
    int r = blockIdx.x, c = threadIdx.x;
    row[c] = emb[r * DM + c];
    __syncthreads();
    float acc = 0.f;
#pragma unroll 8
    for (int k = 0; k < DM; k++) acc += row[k] * W1[k * DM + c];
    g_EW[r * DM + c] = acc;
}

// place edges into CSR slots; flag needed srcs of masked destinations
__global__ void k_place(const int* __restrict__ ei, const int* __restrict__ x) {
    int e = blockIdx.x * blockDim.x + threadIdx.x;
    if (e >= NE) return;
    int s = ei[e];
    int d = ei[NE + e];
    float coef = g_dinv[s] * g_dinv[d];
    int slot = g_off[d] + atomicAdd(&g_cur[d], 1);
    g_ex[slot]    = x[s];
    g_esrc[slot]  = s;
    g_ecoef[slot] = coef;
    if (g_masked[d]) g_needed[s] = 1;
}

// layer-1 gather: out1[i] = b1 + dinv[i]^2*EW[x[i]] + sum coef*EW[x[src]]
// 64 threads per node, float4 per thread; plain coalesced store, no atomics
__global__ void k_gather1(const int* __restrict__ x, const float* __restrict__ b1) {
    int node = blockIdx.x * 4 + (threadIdx.x >> 6);
    if (node >= NN) return;
    if (!g_needed[node]) return;                    // uniform per 64-thread group
    int q = threadIdx.x & 63;

    const float4* EW4 = reinterpret_cast<const float4*>(g_EW);
    float di = g_dinv[node];
    float4 w0 = EW4[x[node] * 64 + q];
    float4 bb = reinterpret_cast<const float4*>(b1)[q];
    float dd = di * di;
    float4 acc = make_float4(bb.x + dd * w0.x, bb.y + dd * w0.y,
                             bb.z + dd * w0.z, bb.w + dd * w0.w);

    int beg = g_off[node];
    int end = beg + g_deg[node] - 1;
    for (int k = beg; k < end; k++) {
        int   xs = g_ex[k];
        float c  = g_ecoef[k];
        float4 w = EW4[xs * 64 + q];
        acc.x += c * w.x; acc.y += c * w.y; acc.z += c * w.z; acc.w += c * w.w;
    }
    reinterpret_cast<float4*>(g_out1)[node * 64 + q] = acc;
}

// layer-2 gather for masked entries only, compact output indexed by j:
//   aggc[j] = dinv^2*relu(out1[node]) + sum coef*relu(out1[src])
__global__ void k_gather2(const int* __restrict__ mask) {
    int gid = blockIdx.x * blockDim.x + threadIdx.x;
    int j = gid >> 6;
    if (j >= NM) return;
    int q = gid & 63;
    int node = mask[j];

    const float4* O4 = reinterpret_cast<const float4*>(g_out1);
    float di = g_dinv[node];
    float dd = di * di;
    float4 h = O4[node * 64 + q];
    float4 acc = make_float4(dd * fmaxf(h.x, 0.f), dd * fmaxf(h.y, 0.f),
                             dd * fmaxf(h.z, 0.f), dd * fmaxf(h.w, 0.f));

    int beg = g_off[node];
    int end = beg + g_deg[node] - 1;
    for (int k = beg; k < end; k++) {
        int   s = g_esrc[k];
        float c = g_ecoef[k];
        float4 hs = O4[s * 64 + q];
        acc.x += c * fmaxf(hs.x, 0.f); acc.y += c * fmaxf(hs.y, 0.f);
        acc.z += c * fmaxf(hs.z, 0.f); acc.w += c * fmaxf(hs.w, 0.f);
    }
    reinterpret_cast<float4*>(g_aggc)[j * 64 + q] = acc;
}

// final: out[j] = log_softmax(aggc[j] @ W2 + b2)
#define FROWS 16
__global__ void k_final(const float* __restrict__ W2,
                        const float* __restrict__ b2,
                        float* __restrict__ out) {
    __shared__ float A[FROWS * DM];
    __shared__ float red[8];
    int c  = threadIdx.x;
    int j0 = blockIdx.x * FROWS;

#pragma unroll
    for (int r = 0; r < FROWS; r++)
        A[r * DM + c] = g_aggc[(j0 + r) * DM + c];
    __syncthreads();

    float bc = b2[c];
    float acc[FROWS];
#pragma unroll
    for (int r = 0; r < FROWS; r++) acc[r] = bc;

    const float4* A4 = reinterpret_cast<const float4*>(A);
#pragma unroll 4
    for (int kk = 0; kk < DM / 4; kk++) {
        float w0 = W2[(4 * kk + 0) * DM + c];
        float w1 = W2[(4 * kk + 1) * DM + c];
        float w2 = W2[(4 * kk + 2) * DM + c];
        float w3 = W2[(4 * kk + 3) * DM + c];
#pragma unroll
        for (int r = 0; r < FROWS; r++) {
            float4 a = A4[r * (DM / 4) + kk];
            acc[r] += a.x * w0 + a.y * w1 + a.z * w2 + a.w * w3;
        }
    }

    int lane = c & 31, wid = c >> 5;
#pragma unroll 1
    for (int r = 0; r < FROWS; r++) {
        float v = acc[r];
#pragma unroll
        for (int o = 16; o; o >>= 1) v = fmaxf(v, __shfl_xor_sync(0xffffffffu, v, o));
        if (lane == 0) red[wid] = v;
        __syncthreads();
        float m = red[0];
#pragma unroll
        for (int w = 1; w < 8; w++) m = fmaxf(m, red[w]);
        __syncthreads();
        float s = __expf(acc[r] - m);
#pragma unroll
        for (int o = 16; o; o >>= 1) s += __shfl_xor_sync(0xffffffffu, s, o);
        if (lane == 0) red[wid] = s;
        __syncthreads();
        float tot = red[0];
#pragma unroll
        for (int w = 1; w < 8; w++) tot += red[w];
        __syncthreads();
        out[(j0 + r) * DM + c] = acc[r] - m - logf(tot);
    }
}

// ---------------- launch -----------------------------------------------------
extern "C" void kernel_launch(void* const* d_in, const int* in_sizes, int n_in,
                              void* d_out, int out_size) {
    const int*   x    = (const int*)d_in[0];   // (100000,1) int32
    const int*   ei   = (const int*)d_in[1];   // (2,800000) int32: [src | dst]
    const int*   mask = (const int*)d_in[2];   // (10000,)   int32
    const float* emb  = (const float*)d_in[3]; // (256,256)
    const float* W1   = (const float*)d_in[4]; // (256,256)
    const float* b1   = (const float*)d_in[5]; // (256,)
    const float* W2   = (const float*)d_in[6]; // (256,256)
    const float* b2   = (const float*)d_in[7]; // (256,)
    float* out = (float*)d_out;                // (10000,256)

    (void)in_sizes; (void)n_in; (void)out_size;

    k_init <<<(NN + 255) / 256, 256>>>();
    k_deg  <<<(NE + 255) / 256, 256>>>(ei);
    k_mark <<<(NM + 255) / 256, 256>>>(mask);
    k_dinv <<<(NN + 255) / 256, 256>>>();
    k_scanA<<<NSB, SB>>>();
    k_scanB<<<1, 256>>>();
    k_scanC<<<NSB, SB>>>();
    k_ew   <<<VC, DM>>>(emb, W1);
    k_place<<<(NE + 255) / 256, 256>>>(ei, x);
    k_gather1<<<(NN + 3) / 4, 256>>>(x, b1);
    k_gather2<<<(NM * 64 + 255) / 256, 256>>>(mask);
    k_final<<<NM / FROWS, DM>>>(W2, b2, out);
}